// round 1
// baseline (speedup 1.0000x reference)
#include <cuda_runtime.h>
#include <math.h>

// ---------------------------------------------------------------------------
// Problem constants (from reference): B=16, C_IN=512, C_OUT=512, K=3, LAT=256,
// H=W=32. Modulated conv reduces to: standard conv (shared raw weights) +
// per-(b,o) output scale s_eff + bias.
// ---------------------------------------------------------------------------
#define BATCH   16
#define CIN     512
#define COUT    512
#define HH      32
#define WW      32
#define LAT     256
#define KR      4608      // CIN * 9

// eq scales
#define EQ_CONV 0.0208333f            /* sqrt(2/4608) -> computed exactly below */
#define EQ_LIN_F (0.08838834764831845f) /* sqrt(2/256) */

// scratch (device globals: allocation-free)
__device__ float g_wt[KR * COUT];        // Wt[r][oc], r = ic*9 + kh*3 + kw  (9.4 MB)
__device__ float g_scale[BATCH * COUT];  // s_eff[b][oc]

// ---------------------------------------------------------------------------
// 1) Weight transpose: W[o][ic][kh][kw] (o-major) -> Wt[r][o], r = ic*9+kh*3+kw
//    Standard 32x32 smem tile transpose; both gmem sides coalesced.
// ---------------------------------------------------------------------------
__global__ void transpose_w_kernel(const float* __restrict__ W) {
    __shared__ float tile[32][33];
    const int rB = blockIdx.x * 32;   // 4608/32 = 144
    const int oB = blockIdx.y * 32;   // 512/32  = 16
    const int tx = threadIdx.x;       // 0..31
    const int ty = threadIdx.y;       // 0..7
#pragma unroll
    for (int i = 0; i < 4; i++) {
        // coalesced read along r
        tile[ty + 8 * i][tx] = W[(size_t)(oB + ty + 8 * i) * KR + rB + tx];
    }
    __syncthreads();
#pragma unroll
    for (int i = 0; i < 4; i++) {
        // coalesced write along o
        g_wt[(size_t)(rB + ty + 8 * i) * COUT + oB + tx] = tile[tx][ty + 8 * i];
    }
}

// ---------------------------------------------------------------------------
// 2) Per-(b,o) effective scale:
//    s[b,o]   = eq_lin * <style_w[b], lin_w[o]> + lin_b[o] + 1 + mod_bias[o]
//    s_eff    = eq_conv * s * rsqrt(s^2 * eq_conv^2 * sum(w_raw[o]^2) + 1e-8)
//    One block per o; 128 threads reduce sum-of-squares; 16 threads do the dots.
// ---------------------------------------------------------------------------
__global__ void scale_kernel(const float* __restrict__ W,
                             const float* __restrict__ style_w,
                             const float* __restrict__ lin_w,
                             const float* __restrict__ lin_b,
                             const float* __restrict__ mod_bias) {
    const int o = blockIdx.x;
    __shared__ float red[128];
    float ss = 0.f;
    const float* wrow = W + (size_t)o * KR;
    for (int i = threadIdx.x; i < KR; i += 128) {
        float v = wrow[i];
        ss += v * v;
    }
    red[threadIdx.x] = ss;
    __syncthreads();
#pragma unroll
    for (int s = 64; s > 0; s >>= 1) {
        if (threadIdx.x < s) red[threadIdx.x] += red[threadIdx.x + s];
        __syncthreads();
    }
    const float sumsq = red[0];
    if (threadIdx.x < BATCH) {
        const int b = threadIdx.x;
        const float* st = style_w + b * LAT;
        const float* lw = lin_w + (size_t)o * LAT;
        float dot = 0.f;
#pragma unroll 8
        for (int l = 0; l < LAT; l++) dot += st[l] * lw[l];
        const float eq_conv = sqrtf(2.0f / (float)KR);
        const float s = dot * EQ_LIN_F + lin_b[o] + 1.0f + mod_bias[o];
        const float se = eq_conv * s * rsqrtf(s * s * eq_conv * eq_conv * sumsq + 1e-8f);
        g_scale[b * COUT + o] = se;
    }
}

// ---------------------------------------------------------------------------
// 3) Main conv as implicit GEMM.
//    Block tile: 128 spatial (one image, 4 rows x 32 cols) x 128 out-channels.
//    K loop: 8 input channels per chunk (72 k-steps of length 1).
//    Thread tile: 8 spatial (8 consecutive cols in one row) x 8 oc.
//    A smem: padded halo patch [8 ic][6 rows][36 cols pad] (cols store w=-1..32).
//    B smem: [72 kidx][128 oc] from the pre-transposed g_wt (coalesced,
//    conflict-free fill; float4 fragment loads).
// ---------------------------------------------------------------------------
__global__ __launch_bounds__(256, 2)
void conv_main_kernel(const float* __restrict__ x,
                      const float* __restrict__ conv_bias,
                      float* __restrict__ out) {
    __shared__ float sA[8][6][36];     // [icl][rr = h-h0+1][cc = w+1], cc 0..33 valid
    __shared__ float sB[72][128];      // [icl*9 + kh*3 + kw][oc local]

    const int t  = threadIdx.x;
    const int tx = t & 15;             // oc group
    const int ty = t >> 4;             // spatial group

    const int mTile = blockIdx.y;      // 0..127
    const int b  = mTile >> 3;
    const int h0 = (mTile & 7) * 4;
    const int ocBase = blockIdx.x * 128;

    const int row = ty >> 2;           // 0..3 within the 4-row band
    const int c0  = (ty & 3) * 8;      // 0,8,16,24
    const int n0  = tx * 8;            // local oc base

    float acc[8][8];
#pragma unroll
    for (int m = 0; m < 8; m++)
#pragma unroll
        for (int n = 0; n < 8; n++) acc[m][n] = 0.f;

    const float* xb = x + (size_t)b * CIN * HH * WW;

    for (int ic0 = 0; ic0 < CIN; ic0 += 8) {
        __syncthreads();  // protect smem from previous chunk's readers

        // --- fill A: 8*6*34 = 1632 elements, coalesced along w ---
        for (int idx = t; idx < 8 * 6 * 34; idx += 256) {
            const int icl = idx / 204;
            const int rem = idx - icl * 204;
            const int rr  = rem / 34;
            const int cc  = rem - rr * 34;
            const int h = h0 + rr - 1;
            const int w = cc - 1;
            float v = 0.f;
            if ((unsigned)h < 32u && (unsigned)w < 32u)
                v = xb[((ic0 + icl) << 10) + (h << 5) + w];
            sA[icl][rr][cc] = v;
        }

        // --- fill B: 72*128 = 9216 elements, coalesced + conflict-free ---
        {
            const float* wp = g_wt + (size_t)(ic0 * 9) * COUT + ocBase;
#pragma unroll
            for (int it = 0; it < 36; it++) {
                const int idx  = it * 256 + t;
                const int kidx = idx >> 7;
                const int o    = idx & 127;
                sB[kidx][o] = wp[kidx * COUT + o];
            }
        }

        __syncthreads();

        // --- compute: 72 k-steps ---
#pragma unroll
        for (int icl = 0; icl < 8; icl++) {
#pragma unroll
            for (int kh = 0; kh < 3; kh++) {
                float aw[10];
#pragma unroll
                for (int u = 0; u < 10; u++)
                    aw[u] = sA[icl][row + kh][c0 + u];   // w = c0+u-1
#pragma unroll
                for (int kw = 0; kw < 3; kw++) {
                    const int kidx = icl * 9 + kh * 3 + kw;
                    float bv[8];
                    *(float4*)&bv[0] = *(const float4*)&sB[kidx][n0];
                    *(float4*)&bv[4] = *(const float4*)&sB[kidx][n0 + 4];
#pragma unroll
                    for (int n = 0; n < 8; n++)
#pragma unroll
                        for (int m = 0; m < 8; m++)
                            acc[m][n] += aw[m + kw] * bv[n];
                }
            }
        }
    }

    // --- epilogue: out = s_eff[b,oc] * y + bias[oc], vectorized stores ---
    const int h = h0 + row;
#pragma unroll
    for (int n = 0; n < 8; n++) {
        const int oc = ocBase + n0 + n;
        const float sc = g_scale[(b << 9) + oc];
        const float bs = conv_bias[oc];
        float4 r0, r1;
        r0.x = acc[0][n] * sc + bs;  r0.y = acc[1][n] * sc + bs;
        r0.z = acc[2][n] * sc + bs;  r0.w = acc[3][n] * sc + bs;
        r1.x = acc[4][n] * sc + bs;  r1.y = acc[5][n] * sc + bs;
        r1.z = acc[6][n] * sc + bs;  r1.w = acc[7][n] * sc + bs;
        const size_t off = (((size_t)(b * COUT + oc) * HH) + h) * WW + c0;
        *(float4*)&out[off]     = r0;
        *(float4*)&out[off + 4] = r1;
    }
}

// ---------------------------------------------------------------------------
// Launch: inputs in setup_inputs order:
//   0 x[16,512,32,32] 1 style_w[16,256] 2 conv_weight[512,512,3,3]
//   3 lin_w[512,256]  4 lin_b[512]      5 mod_bias[512] 6 conv_bias[512]
// ---------------------------------------------------------------------------
extern "C" void kernel_launch(void* const* d_in, const int* in_sizes, int n_in,
                              void* d_out, int out_size) {
    const float* x         = (const float*)d_in[0];
    const float* style_w   = (const float*)d_in[1];
    const float* conv_w    = (const float*)d_in[2];
    const float* lin_w     = (const float*)d_in[3];
    const float* lin_b     = (const float*)d_in[4];
    const float* mod_bias  = (const float*)d_in[5];
    const float* conv_bias = (const float*)d_in[6];
    float* out = (float*)d_out;

    transpose_w_kernel<<<dim3(KR / 32, COUT / 32), dim3(32, 8)>>>(conv_w);
    scale_kernel<<<COUT, 128>>>(conv_w, style_w, lin_w, lin_b, mod_bias);
    conv_main_kernel<<<dim3(COUT / 128, BATCH * (HH / 4)), 256>>>(x, conv_bias, out);
}

// round 2
// speedup vs baseline: 1.2386x; 1.2386x over previous
#include <cuda_runtime.h>
#include <math.h>

// ---------------------------------------------------------------------------
// B=16, C_IN=512, C_OUT=512, K=3, LAT=256, H=W=32.
// Modulated conv == standard conv (shared raw weights) + per-(b,o) scale.
// Mainloop now uses packed fma.rn.f32x2 (FFMA2) -> 2 FMAs/instr, restoring
// full 128 FMA/cyc/SM (3-reg FFMA is half-rate on Blackwell).
// ---------------------------------------------------------------------------
#define BATCH   16
#define CIN     512
#define COUT    512
#define HH      32
#define WW      32
#define LAT     256
#define KR      4608      // CIN * 9

#define EQ_LIN_F (0.08838834764831845f) /* sqrt(2/256) */

typedef unsigned long long u64;

#define FMA_F32X2(d, a, b, c) \
    asm("fma.rn.f32x2 %0, %1, %2, %3;" : "=l"(d) : "l"(a), "l"(b), "l"(c))
#define PACK_F32X2(out, lo, hi) \
    asm("mov.b64 %0, {%1, %2};" : "=l"(out) : "f"(lo), "f"(hi))
#define UNPACK_F32X2(lo, hi, in) \
    asm("mov.b64 {%0, %1}, %2;" : "=f"(lo), "=f"(hi) : "l"(in))

// scratch (device globals: allocation-free)
__device__ float g_wt[KR * COUT];        // Wt[r][oc], r = ic*9 + kh*3 + kw
__device__ float g_scale[BATCH * COUT];  // s_eff[b][oc]

// ---------------------------------------------------------------------------
// 1) Weight transpose: W[o][r] -> Wt[r][o]
// ---------------------------------------------------------------------------
__global__ void transpose_w_kernel(const float* __restrict__ W) {
    __shared__ float tile[32][33];
    const int rB = blockIdx.x * 32;
    const int oB = blockIdx.y * 32;
    const int tx = threadIdx.x;
    const int ty = threadIdx.y;
#pragma unroll
    for (int i = 0; i < 4; i++)
        tile[ty + 8 * i][tx] = W[(size_t)(oB + ty + 8 * i) * KR + rB + tx];
    __syncthreads();
#pragma unroll
    for (int i = 0; i < 4; i++)
        g_wt[(size_t)(rB + ty + 8 * i) * COUT + oB + tx] = tile[tx][ty + 8 * i];
}

// ---------------------------------------------------------------------------
// 2) Per-(b,o) effective scale.
// ---------------------------------------------------------------------------
__global__ void scale_kernel(const float* __restrict__ W,
                             const float* __restrict__ style_w,
                             const float* __restrict__ lin_w,
                             const float* __restrict__ lin_b,
                             const float* __restrict__ mod_bias) {
    const int o = blockIdx.x;
    __shared__ float red[128];
    float ss = 0.f;
    const float* wrow = W + (size_t)o * KR;
    for (int i = threadIdx.x; i < KR; i += 128) {
        float v = wrow[i];
        ss += v * v;
    }
    red[threadIdx.x] = ss;
    __syncthreads();
#pragma unroll
    for (int s = 64; s > 0; s >>= 1) {
        if (threadIdx.x < s) red[threadIdx.x] += red[threadIdx.x + s];
        __syncthreads();
    }
    const float sumsq = red[0];
    if (threadIdx.x < BATCH) {
        const int b = threadIdx.x;
        const float* st = style_w + b * LAT;
        const float* lw = lin_w + (size_t)o * LAT;
        float dot = 0.f;
#pragma unroll 8
        for (int l = 0; l < LAT; l++) dot += st[l] * lw[l];
        const float eq_conv = sqrtf(2.0f / (float)KR);
        const float s = dot * EQ_LIN_F + lin_b[o] + 1.0f + mod_bias[o];
        const float se = eq_conv * s * rsqrtf(s * s * eq_conv * eq_conv * sumsq + 1e-8f);
        g_scale[b * COUT + o] = se;
    }
}

// ---------------------------------------------------------------------------
// 3) Main conv as implicit GEMM with FFMA2 mainloop.
//    Block: 128 spatial (1 image, 4 rows x 32 cols) x 128 oc; 256 threads;
//    thread tile 8 spatial x 8 oc. Accumulators packed along oc into f32x2:
//    B pairs come straight from smem (64-bit aligned), A is a (a,a) dup pack.
// ---------------------------------------------------------------------------
__global__ __launch_bounds__(256, 2)
void conv_main_kernel(const float* __restrict__ x,
                      const float* __restrict__ conv_bias,
                      float* __restrict__ out) {
    __shared__ float sA[8][6][36];     // [icl][rr=h-h0+1][cc=w+1]
    __shared__ float sB[72][128];      // [icl*9+kh*3+kw][oc local]

    const int t  = threadIdx.x;
    const int tx = t & 15;             // oc group
    const int ty = t >> 4;             // spatial group

    const int mTile = blockIdx.y;
    const int b  = mTile >> 3;
    const int h0 = (mTile & 7) * 4;
    const int ocBase = blockIdx.x * 128;

    const int row = ty >> 2;
    const int c0  = (ty & 3) * 8;
    const int n0  = tx * 8;

    u64 accp[8][4];                    // [m][n-pair]
#pragma unroll
    for (int m = 0; m < 8; m++)
#pragma unroll
        for (int np = 0; np < 4; np++) accp[m][np] = 0ULL;

    const float* xb = x + (size_t)b * CIN * HH * WW;

    for (int ic0 = 0; ic0 < CIN; ic0 += 8) {
        __syncthreads();

        // --- fill A: 8*6*34 elements, coalesced along w ---
        for (int idx = t; idx < 8 * 6 * 34; idx += 256) {
            const int icl = idx / 204;
            const int rem = idx - icl * 204;
            const int rr  = rem / 34;
            const int cc  = rem - rr * 34;
            const int h = h0 + rr - 1;
            const int w = cc - 1;
            float v = 0.f;
            if ((unsigned)h < 32u && (unsigned)w < 32u)
                v = xb[((ic0 + icl) << 10) + (h << 5) + w];
            sA[icl][rr][cc] = v;
        }

        // --- fill B: 72*128 elements, coalesced + conflict-free ---
        {
            const float* wp = g_wt + (size_t)(ic0 * 9) * COUT + ocBase;
#pragma unroll
            for (int it = 0; it < 36; it++) {
                const int idx  = it * 256 + t;
                const int kidx = idx >> 7;
                const int o    = idx & 127;
                sB[kidx][o] = wp[kidx * COUT + o];
            }
        }

        __syncthreads();

        // --- compute: 72 k-steps, FFMA2 ---
#pragma unroll
        for (int icl = 0; icl < 8; icl++) {
#pragma unroll
            for (int kh = 0; kh < 3; kh++) {
                float aw[10];
#pragma unroll
                for (int u = 0; u < 10; u++)
                    aw[u] = sA[icl][row + kh][c0 + u];   // w = c0+u-1
#pragma unroll
                for (int kw = 0; kw < 3; kw++) {
                    const int kidx = icl * 9 + kh * 3 + kw;
                    // 4 oc pairs straight from smem (32B-aligned)
                    const u64* bp = (const u64*)&sB[kidx][n0];
                    u64 b2[4];
                    b2[0] = bp[0]; b2[1] = bp[1]; b2[2] = bp[2]; b2[3] = bp[3];
                    u64 a2[8];
#pragma unroll
                    for (int m = 0; m < 8; m++)
                        PACK_F32X2(a2[m], aw[m + kw], aw[m + kw]);
#pragma unroll
                    for (int m = 0; m < 8; m++)
#pragma unroll
                        for (int np = 0; np < 4; np++)
                            FMA_F32X2(accp[m][np], a2[m], b2[np], accp[m][np]);
                }
            }
        }
    }

    // --- epilogue: out = s_eff[b,oc] * y + bias[oc] ---
    const int h = h0 + row;
#pragma unroll
    for (int np = 0; np < 4; np++) {
        const int oc0 = ocBase + n0 + 2 * np;
        const float sc0 = g_scale[(b << 9) + oc0];
        const float sc1 = g_scale[(b << 9) + oc0 + 1];
        const float bs0 = conv_bias[oc0];
        const float bs1 = conv_bias[oc0 + 1];
        float y0[8], y1[8];
#pragma unroll
        for (int m = 0; m < 8; m++) {
            float lo, hi;
            UNPACK_F32X2(lo, hi, accp[m][np]);
            y0[m] = lo * sc0 + bs0;
            y1[m] = hi * sc1 + bs1;
        }
        const size_t base0 = (((size_t)(b * COUT + oc0) * HH) + h) * WW + c0;
        const size_t base1 = (((size_t)(b * COUT + oc0 + 1) * HH) + h) * WW + c0;
        *(float4*)&out[base0]     = make_float4(y0[0], y0[1], y0[2], y0[3]);
        *(float4*)&out[base0 + 4] = make_float4(y0[4], y0[5], y0[6], y0[7]);
        *(float4*)&out[base1]     = make_float4(y1[0], y1[1], y1[2], y1[3]);
        *(float4*)&out[base1 + 4] = make_float4(y1[4], y1[5], y1[6], y1[7]);
    }
}

// ---------------------------------------------------------------------------
// Launch. Inputs: 0 x, 1 style_w, 2 conv_weight, 3 lin_w, 4 lin_b,
//                 5 mod_bias, 6 conv_bias
// ---------------------------------------------------------------------------
extern "C" void kernel_launch(void* const* d_in, const int* in_sizes, int n_in,
                              void* d_out, int out_size) {
    const float* x         = (const float*)d_in[0];
    const float* style_w   = (const float*)d_in[1];
    const float* conv_w    = (const float*)d_in[2];
    const float* lin_w     = (const float*)d_in[3];
    const float* lin_b     = (const float*)d_in[4];
    const float* mod_bias  = (const float*)d_in[5];
    const float* conv_bias = (const float*)d_in[6];
    float* out = (float*)d_out;

    transpose_w_kernel<<<dim3(KR / 32, COUT / 32), dim3(32, 8)>>>(conv_w);
    scale_kernel<<<COUT, 128>>>(conv_w, style_w, lin_w, lin_b, mod_bias);
    conv_main_kernel<<<dim3(COUT / 128, BATCH * (HH / 4)), 256>>>(x, conv_bias, out);
}

// round 4
// speedup vs baseline: 1.4847x; 1.1987x over previous
#include <cuda_runtime.h>
#include <math.h>

// ---------------------------------------------------------------------------
// B=16, C_IN=512, C_OUT=512, K=3, LAT=256, H=W=32.
// Modulated conv == standard conv (shared raw weights) + per-(b,o) scale.
// FFMA2 mainloop + 2-stage cp.async pipeline (4-input-channel chunks).
// ---------------------------------------------------------------------------
#define BATCH   16
#define CIN     512
#define COUT    512
#define HH      32
#define WW      32
#define LAT     256
#define KR      4608      // CIN * 9
#define ICC     4         // input channels per chunk
#define NCHUNK  (CIN / ICC)   // 128
#define KC      (ICC * 9)     // 36 k-rows per chunk
#define A_ELEMS (ICC * 6 * 34)    // 816 valid-enumerated A entries per chunk
#define A_SMEMF (ICC * 6 * 36)    // 864 floats per A stage

#define EQ_LIN_F (0.08838834764831845f) /* sqrt(2/256) */

typedef unsigned long long u64;

#define FMA_F32X2(d, a, b, c) \
    asm("fma.rn.f32x2 %0, %1, %2, %3;" : "=l"(d) : "l"(a), "l"(b), "l"(c))
#define PACK_F32X2(out, lo, hi) \
    asm("mov.b64 %0, {%1, %2};" : "=l"(out) : "f"(lo), "f"(hi))
#define UNPACK_F32X2(lo, hi, in) \
    asm("mov.b64 {%0, %1}, %2;" : "=f"(lo), "=f"(hi) : "l"(in))

#define CP_ASYNC_16(dst_u32, src) \
    asm volatile("cp.async.cg.shared.global [%0], [%1], 16;" :: "r"(dst_u32), "l"(src))
#define CP_ASYNC_4(dst_u32, src) \
    asm volatile("cp.async.ca.shared.global [%0], [%1], 4;" :: "r"(dst_u32), "l"(src))
#define CP_ASYNC_COMMIT() asm volatile("cp.async.commit_group;")
#define CP_ASYNC_WAIT0()  asm volatile("cp.async.wait_group 0;" ::: "memory")

// scratch (device globals: allocation-free)
__device__ float g_wt[KR * COUT];        // Wt[r][oc], r = ic*9 + kh*3 + kw
__device__ float g_scale[BATCH * COUT];  // s_eff[b][oc]

// ---------------------------------------------------------------------------
// 1) Weight transpose: W[o][r] -> Wt[r][o]
// ---------------------------------------------------------------------------
__global__ void transpose_w_kernel(const float* __restrict__ W) {
    __shared__ float tile[32][33];
    const int rB = blockIdx.x * 32;
    const int oB = blockIdx.y * 32;
    const int tx = threadIdx.x;
    const int ty = threadIdx.y;
#pragma unroll
    for (int i = 0; i < 4; i++)
        tile[ty + 8 * i][tx] = W[(size_t)(oB + ty + 8 * i) * KR + rB + tx];
    __syncthreads();
#pragma unroll
    for (int i = 0; i < 4; i++)
        g_wt[(size_t)(rB + ty + 8 * i) * COUT + oB + tx] = tile[tx][ty + 8 * i];
}

// ---------------------------------------------------------------------------
// 2) Per-(b,o) effective scale.
// ---------------------------------------------------------------------------
__global__ void scale_kernel(const float* __restrict__ W,
                             const float* __restrict__ style_w,
                             const float* __restrict__ lin_w,
                             const float* __restrict__ lin_b,
                             const float* __restrict__ mod_bias) {
    const int o = blockIdx.x;
    __shared__ float red[128];
    float ss = 0.f;
    const float* wrow = W + (size_t)o * KR;
    for (int i = threadIdx.x; i < KR; i += 128) {
        float v = wrow[i];
        ss += v * v;
    }
    red[threadIdx.x] = ss;
    __syncthreads();
#pragma unroll
    for (int s = 64; s > 0; s >>= 1) {
        if (threadIdx.x < s) red[threadIdx.x] += red[threadIdx.x + s];
        __syncthreads();
    }
    const float sumsq = red[0];
    if (threadIdx.x < BATCH) {
        const int b = threadIdx.x;
        const float* st = style_w + b * LAT;
        const float* lw = lin_w + (size_t)o * LAT;
        float dot = 0.f;
#pragma unroll 8
        for (int l = 0; l < LAT; l++) dot += st[l] * lw[l];
        const float eq_conv = sqrtf(2.0f / (float)KR);
        const float s = dot * EQ_LIN_F + lin_b[o] + 1.0f + mod_bias[o];
        const float se = eq_conv * s * rsqrtf(s * s * eq_conv * eq_conv * sumsq + 1e-8f);
        g_scale[b * COUT + o] = se;
    }
}

// ---------------------------------------------------------------------------
// 3) Main conv: implicit GEMM, FFMA2 mainloop, 2-stage cp.async pipeline.
//    Block: 128 spatial (1 image, 4 rows x 32 cols) x 128 oc; 256 threads;
//    thread tile 8 spatial x 8 oc (accs packed along oc into f32x2).
// ---------------------------------------------------------------------------
__global__ __launch_bounds__(256, 2)
void conv_main_kernel(const float* __restrict__ x,
                      const float* __restrict__ conv_bias,
                      float* __restrict__ out) {
    __shared__ __align__(16) float sB[2][KC][128];       // 2*36*128*4 = 36864 B
    __shared__ __align__(16) float sA[2][ICC][6][36];    // 2*864*4    =  6912 B

    const int t  = threadIdx.x;
    const int tx = t & 15;             // oc group
    const int ty = t >> 4;             // spatial group

    const int mTile = blockIdx.y;
    const int b  = mTile >> 3;
    const int h0 = (mTile & 7) * 4;
    const int ocBase = blockIdx.x * 128;

    const int row = ty >> 2;           // 0..3
    const int c0  = (ty & 3) * 8;      // 0,8,16,24
    const int n0  = tx * 8;

    u64 accp[8][4];
#pragma unroll
    for (int m = 0; m < 8; m++)
#pragma unroll
        for (int np = 0; np < 4; np++) accp[m][np] = 0ULL;

    const float* xb = x + (size_t)b * CIN * HH * WW;
    const float* wB = g_wt + ocBase;   // + r*COUT

    // --- prologue: zero both A stages (halo entries stay 0 forever) ---
    {
        float* pz = &sA[0][0][0][0];
        for (int i = t; i < 2 * A_SMEMF; i += 256) pz[i] = 0.f;
    }
    __syncthreads();

    // fill helper (prologue + steady state)
    auto fill_stage = [&](int s, int ic0) {
        // B: 36 rows x 128 oc = 1152 float4, cp.async.cg 16B
        {
            const float* wp = wB + (size_t)(ic0 * 9) * COUT;
            unsigned int dstB = (unsigned int)__cvta_generic_to_shared(&sB[s][0][0]);
#pragma unroll
            for (int i = t; i < KC * 32; i += 256) {   // 1152
                const int kidx = i >> 5;
                const int o4   = (i & 31) << 2;
                CP_ASYNC_16(dstB + (unsigned)((kidx << 7) + o4) * 4u,
                            wp + (size_t)kidx * COUT + o4);
            }
        }
        // A: valid interior entries only (halo pre-zeroed), cp.async.ca 4B
        {
            unsigned int dstA = (unsigned int)__cvta_generic_to_shared(&sA[s][0][0][0]);
#pragma unroll
            for (int i = t; i < A_ELEMS; i += 256) {   // 816
                const int icl = i / 204;
                const int rem = i - icl * 204;
                const int rr  = rem / 34;
                const int cc  = rem - rr * 34;
                const int h = h0 + rr - 1;
                const int w = cc - 1;
                if ((unsigned)h < 32u && (unsigned)w < 32u) {
                    CP_ASYNC_4(dstA + (unsigned)(icl * 216 + rr * 36 + cc) * 4u,
                               xb + ((ic0 + icl) << 10) + (h << 5) + w);
                }
            }
        }
        CP_ASYNC_COMMIT();
    };

    fill_stage(0, 0);

    for (int c = 0; c < NCHUNK; c++) {
        const int s = c & 1;
        CP_ASYNC_WAIT0();
        __syncthreads();               // stage s ready for all; s^1 free
        if (c + 1 < NCHUNK) fill_stage(s ^ 1, (c + 1) * ICC);

        // --- compute chunk c from stage s ---
#pragma unroll
        for (int icl = 0; icl < ICC; icl++) {
#pragma unroll
            for (int kh = 0; kh < 3; kh++) {
                float aw[10];
                *(float4*)&aw[0] = *(const float4*)&sA[s][icl][row + kh][c0];
                *(float4*)&aw[4] = *(const float4*)&sA[s][icl][row + kh][c0 + 4];
                aw[8] = sA[s][icl][row + kh][c0 + 8];
                aw[9] = sA[s][icl][row + kh][c0 + 9];
#pragma unroll
                for (int kw = 0; kw < 3; kw++) {
                    const int kidx = icl * 9 + kh * 3 + kw;
                    u64 b2[4];
                    {
                        const ulonglong2 p0 = *(const ulonglong2*)&sB[s][kidx][n0];
                        const ulonglong2 p1 = *(const ulonglong2*)&sB[s][kidx][n0 + 4];
                        b2[0] = p0.x; b2[1] = p0.y; b2[2] = p1.x; b2[3] = p1.y;
                    }
                    u64 a2[8];
#pragma unroll
                    for (int m = 0; m < 8; m++)
                        PACK_F32X2(a2[m], aw[m + kw], aw[m + kw]);
#pragma unroll
                    for (int m = 0; m < 8; m++)
#pragma unroll
                        for (int np = 0; np < 4; np++)
                            FMA_F32X2(accp[m][np], a2[m], b2[np], accp[m][np]);
                }
            }
        }
    }

    // --- epilogue: out = s_eff[b,oc] * y + bias[oc] ---
    const int h = h0 + row;
    const float* scRow = g_scale + (b << 9);
#pragma unroll
    for (int np = 0; np < 4; np++) {
        const int oc0 = ocBase + n0 + 2 * np;
        const float sc0 = scRow[oc0];
        const float sc1 = scRow[oc0 + 1];
        const float bs0 = conv_bias[oc0];
        const float bs1 = conv_bias[oc0 + 1];
        float y0[8], y1[8];
#pragma unroll
        for (int m = 0; m < 8; m++) {
            float lo, hi;
            UNPACK_F32X2(lo, hi, accp[m][np]);
            y0[m] = lo * sc0 + bs0;
            y1[m] = hi * sc1 + bs1;
        }
        const size_t base0 = (((size_t)(b * COUT + oc0) * HH) + h) * WW + c0;
        const size_t base1 = (((size_t)(b * COUT + oc0 + 1) * HH) + h) * WW + c0;
        *(float4*)&out[base0]     = make_float4(y0[0], y0[1], y0[2], y0[3]);
        *(float4*)&out[base0 + 4] = make_float4(y0[4], y0[5], y0[6], y0[7]);
        *(float4*)&out[base1]     = make_float4(y1[0], y1[1], y1[2], y1[3]);
        *(float4*)&out[base1 + 4] = make_float4(y1[4], y1[5], y1[6], y1[7]);
    }
}

// ---------------------------------------------------------------------------
// Launch. Inputs: 0 x, 1 style_w, 2 conv_weight, 3 lin_w, 4 lin_b,
//                 5 mod_bias, 6 conv_bias
// ---------------------------------------------------------------------------
extern "C" void kernel_launch(void* const* d_in, const int* in_sizes, int n_in,
                              void* d_out, int out_size) {
    const float* x         = (const float*)d_in[0];
    const float* style_w   = (const float*)d_in[1];
    const float* conv_w    = (const float*)d_in[2];
    const float* lin_w     = (const float*)d_in[3];
    const float* lin_b     = (const float*)d_in[4];
    const float* mod_bias  = (const float*)d_in[5];
    const float* conv_bias = (const float*)d_in[6];
    float* out = (float*)d_out;

    transpose_w_kernel<<<dim3(KR / 32, COUT / 32), dim3(32, 8)>>>(conv_w);
    scale_kernel<<<COUT, 128>>>(conv_w, style_w, lin_w, lin_b, mod_bias);
    conv_main_kernel<<<dim3(COUT / 128, BATCH * (HH / 4)), 256>>>(x, conv_bias, out);
}

// round 8
// speedup vs baseline: 2.0615x; 1.3885x over previous
#include <cuda_runtime.h>
#include <cuda_bf16.h>
#include <stdint.h>
#include <math.h>

// ---------------------------------------------------------------------------
// B=16, C_IN=512, C_OUT=512, K=3, LAT=256, H=W=32.
// Modulated conv == plain conv (raw weights) + per-(b,oc) scale + bias.
// Conv as implicit GEMM on tensor cores via baseline mma.sync (sm_100 target
// rejects tcgen05 'a'-features). 3-pass bf16 hi/lo split:
//   out = xh*wh + xh*wl + xl*wh   (drops xl*wl ~ 2^-16 relative)
// Round-7 fix: ldmatrix addresses must swizzle AFTER adding the k-step
// offset (kb occupies the XOR-target bits; adding to a swizzled base can
// carry into the row index -> reads of unwritten smem -> NaN).
// ---------------------------------------------------------------------------
#define BATCH   16
#define CIN     512
#define COUT    512
#define LAT     256
#define KR      4608
#define XP      34                   // padded plane 34x34 (zero border)
#define XPP     (XP * XP)            // 1156
#define NXP     (BATCH * CIN * XPP)
#define NW      (COUT * CIN)         // per tap

#define EQ_LIN_F 0.08838834764831845f

// ---- device scratch (allocation-free) ----
__device__ __nv_bfloat16 g_xph[NXP];
__device__ __nv_bfloat16 g_xpl[NXP];
__device__ __nv_bfloat16 g_wh[9 * NW];   // [tap][oc][ic]
__device__ __nv_bfloat16 g_wl[9 * NW];
__device__ float         g_scale[BATCH * COUT];

// ---------------------------------------------------------------------------
// helpers (baseline PTX only: ldmatrix sm_75+, mma.sync bf16 sm_80+, cp.async)
// ---------------------------------------------------------------------------
__device__ __forceinline__ uint32_t smem_u32(const void* p) {
    uint32_t a;
    asm("{ .reg .u64 t; cvta.to.shared.u64 t, %1; cvt.u32.u64 %0, t; }"
        : "=r"(a) : "l"(p));
    return a;
}
#define SW128(o) ((o) ^ ((((unsigned)(o)) >> 3) & 0x70u))

#define LDM_X4(r0, r1, r2, r3, a) \
    asm volatile("ldmatrix.sync.aligned.m8n8.x4.shared.b16 {%0,%1,%2,%3}, [%4];" \
        : "=r"(r0), "=r"(r1), "=r"(r2), "=r"(r3) : "r"(a))
#define LDM_X2(r0, r1, a) \
    asm volatile("ldmatrix.sync.aligned.m8n8.x2.shared.b16 {%0,%1}, [%2];" \
        : "=r"(r0), "=r"(r1) : "r"(a))

#define MMA16816(d, a, b) \
    asm volatile("mma.sync.aligned.m16n8k16.row.col.f32.bf16.bf16.f32 " \
        "{%0,%1,%2,%3}, {%4,%5,%6,%7}, {%8,%9}, {%0,%1,%2,%3};" \
        : "+f"((d)[0]), "+f"((d)[1]), "+f"((d)[2]), "+f"((d)[3]) \
        : "r"((a)[0]), "r"((a)[1]), "r"((a)[2]), "r"((a)[3]), \
          "r"((b)[0]), "r"((b)[1]))

#define CP16(dst, src) \
    asm volatile("cp.async.cg.shared.global [%0], [%1], 16;" :: "r"(dst), "l"(src))
#define CP_COMMIT() asm volatile("cp.async.commit_group;")
#define CP_WAIT0()  asm volatile("cp.async.wait_group 0;" ::: "memory")

// ---------------------------------------------------------------------------
// 1) split + pad x -> bf16 hi/lo padded planes [b*ic][34][34]
// ---------------------------------------------------------------------------
__global__ void split_x_kernel(const float* __restrict__ x) {
    int i = blockIdx.x * blockDim.x + threadIdx.x;
    if (i >= NXP) return;
    const int wp = i % XP;
    const int r  = i / XP;
    const int hp = r % XP;
    const int bc = r / XP;
    float v = 0.f;
    if (hp >= 1 && hp <= 32 && wp >= 1 && wp <= 32)
        v = x[(size_t)bc * 1024 + (hp - 1) * 32 + (wp - 1)];
    const __nv_bfloat16 h = __float2bfloat16(v);
    g_xph[i] = h;
    g_xpl[i] = __float2bfloat16(v - __bfloat162float(h));
}

// ---------------------------------------------------------------------------
// 2) split + per-tap transpose weights -> g_wh/g_wl [tap][oc][ic]
// ---------------------------------------------------------------------------
__global__ void split_w_kernel(const float* __restrict__ w) {
    int i = blockIdx.x * blockDim.x + threadIdx.x;   // oc*512 + ic
    if (i >= NW) return;
    const float* src = w + (size_t)i * 9;
#pragma unroll
    for (int t = 0; t < 9; t++) {
        const float v = src[t];
        const __nv_bfloat16 h = __float2bfloat16(v);
        g_wh[(size_t)t * NW + i] = h;
        g_wl[(size_t)t * NW + i] = __float2bfloat16(v - __bfloat162float(h));
    }
}

// ---------------------------------------------------------------------------
// 3) per-(b,oc) effective scale (verified)
// ---------------------------------------------------------------------------
__global__ void scale_kernel(const float* __restrict__ W,
                             const float* __restrict__ style_w,
                             const float* __restrict__ lin_w,
                             const float* __restrict__ lin_b,
                             const float* __restrict__ mod_bias) {
    const int o = blockIdx.x;
    __shared__ float red[128];
    float ss = 0.f;
    const float* wrow = W + (size_t)o * KR;
    for (int i = threadIdx.x; i < KR; i += 128) {
        float v = wrow[i];
        ss += v * v;
    }
    red[threadIdx.x] = ss;
    __syncthreads();
#pragma unroll
    for (int s = 64; s > 0; s >>= 1) {
        if (threadIdx.x < s) red[threadIdx.x] += red[threadIdx.x + s];
        __syncthreads();
    }
    const float sumsq = red[0];
    if (threadIdx.x < BATCH) {
        const int b = threadIdx.x;
        const float* st = style_w + b * LAT;
        const float* lw = lin_w + (size_t)o * LAT;
        float dot = 0.f;
#pragma unroll 8
        for (int l = 0; l < LAT; l++) dot += st[l] * lw[l];
        const float eq_conv = sqrtf(2.0f / (float)KR);
        const float s = dot * EQ_LIN_F + lin_b[o] + 1.0f + mod_bias[o];
        g_scale[b * COUT + o] =
            eq_conv * s * rsqrtf(s * s * eq_conv * eq_conv * sumsq + 1e-8f);
    }
}

// ---------------------------------------------------------------------------
// 4) main mma.sync kernel.
//    CTA: M=128 spatial (b, 4 rows x 32 cols) x N=128 oc. Grid (4, 128).
//    8 warps as 2(M) x 4(N) -> 64x32 warp tiles; m16n8k16 bf16 frags.
//    K loop: 8 ic-chunks(64) x 9 taps = 72 iters. Per iter: build Ah/Al
//    im2col (SW128 m-major), cp.async Bh/Bl, then 4 k16-steps x 3 passes.
// ---------------------------------------------------------------------------
#define SMEM_SZ (65536 + 1024)

__global__ __launch_bounds__(256, 2)
void conv_mma_kernel(const float* __restrict__ conv_bias, float* __restrict__ out) {
    extern __shared__ __align__(1024) char dsm[];
    const uint32_t sb = smem_u32(dsm);
    const uint32_t tb = (sb + 1023u) & ~1023u;
    char* tbp = dsm + (tb - sb);                 // == sAh as generic ptr

    const uint32_t sAh = tb;                     // [128 m][64 k] bf16, SW128
    const uint32_t sBh = tb + 32768;             // [128 n][64 k] bf16, SW128
    const uint32_t sBl = tb + 49152;

    const int t    = threadIdx.x;
    const int wid  = t >> 5, lane = t & 31;
    const int ocBase = blockIdx.x * 128;
    const int mT = blockIdx.y;
    const int b  = mT >> 3;
    const int h0 = (mT & 7) * 4;

    const int wm0 = (wid & 1) * 64;
    const int wn0 = (wid >> 1) * 32;

    // Unswizzled fragment offsets + per-fragment row-XOR.
    // Correct per-use address: (off + kb) ^ rxor. low7(off)=ha*16<=16 and
    // kb<=96 -> no carry into row bits; rxor constant per fragment (row bits
    // [9:7] fixed). +16384 (lo tile) is outside both swizzle masks.
    uint32_t aOff[4], aXor[4], bOff[4], bXor[4];
    {
        const int rA = lane & 15;
        const int ha = lane >> 4;                // 0/1 -> k+8 half
#pragma unroll
        for (int tm = 0; tm < 4; tm++) {
            const uint32_t off = (uint32_t)(wm0 + tm * 16 + rA) * 128u + ha * 16u;
            aOff[tm] = sAh + off;
            aXor[tm] = (off >> 3) & 0x70u;
        }
        const int rB = lane & 7;
        const int hb = (lane >> 3) & 1;
#pragma unroll
        for (int tn = 0; tn < 4; tn++) {
            const uint32_t off = (uint32_t)(wn0 + tn * 8 + rB) * 128u + hb * 16u;
            bOff[tn] = sBh + off;
            bXor[tn] = (off >> 3) & 0x70u;
        }
    }

    float acc[4][4][4];
#pragma unroll
    for (int i = 0; i < 4; i++)
#pragma unroll
        for (int j = 0; j < 4; j++)
#pragma unroll
            for (int k = 0; k < 4; k++) acc[i][j][k] = 0.f;

    const __nv_bfloat16* xh = g_xph + (size_t)b * CIN * XPP;
    const __nv_bfloat16* xl = g_xpl + (size_t)b * CIN * XPP;

    for (int it = 0; it < 72; it++) {
        const int ch  = it / 9;
        const int tap = it - ch * 9;
        const int ic0 = ch * 64;
        const int dh = tap / 3, dw = tap - dh * 3;

        __syncthreads();   // previous compute done before overwriting tiles

        // ---- build A (im2col hi+lo): [128 m][64 ic], SW128 ----
        {
            const int pbase = (h0 + dh) * XP + dw;
            for (int i = t; i < 8192; i += 256) {
                const int ic = i >> 7;
                const int m  = i & 127;
                const uint32_t sa = SW128((uint32_t)(m << 7) + (ic << 1));
                const size_t g = (size_t)(ic0 + ic) * XPP + pbase
                               + (m >> 5) * XP + (m & 31);
                *(__nv_bfloat16*)(tbp + sa)         = xh[g];
                *(__nv_bfloat16*)(tbp + 16384 + sa) = xl[g];
            }
        }
        // ---- B tiles via cp.async: [128 oc][64 ic] x2 ----
        {
            const size_t wof = (size_t)tap * NW + (size_t)ocBase * CIN + ic0;
            for (int i = t; i < 2048; i += 256) {
                const int v   = i >> 10;          // 0=hi, 1=lo
                const int oc  = (i >> 3) & 127;
                const int icw = i & 7;
                const __nv_bfloat16* src =
                    (v ? g_wl : g_wh) + wof + (size_t)oc * CIN + (icw << 3);
                const uint32_t dst = (v ? sBl : sBh)
                                   + SW128((uint32_t)(oc << 7) + (icw << 4));
                CP16(dst, src);
            }
            CP_COMMIT();
            CP_WAIT0();
        }
        __syncthreads();

        // ---- compute: 4 k16-steps x {AhBh, AhBl, AlBh} ----
#pragma unroll
        for (int ks = 0; ks < 4; ks++) {
            const uint32_t kb = ks * 32;          // 16 bf16 = 32 bytes
            uint32_t a[4][4], bh[4][2], bl[4][2];
#pragma unroll
            for (int tn = 0; tn < 4; tn++)
                LDM_X2(bh[tn][0], bh[tn][1], (bOff[tn] + kb) ^ bXor[tn]);
#pragma unroll
            for (int tm = 0; tm < 4; tm++)
                LDM_X4(a[tm][0], a[tm][1], a[tm][2], a[tm][3],
                       (aOff[tm] + kb) ^ aXor[tm]);
#pragma unroll
            for (int tm = 0; tm < 4; tm++)
#pragma unroll
                for (int tn = 0; tn < 4; tn++)
                    MMA16816(acc[tm][tn], a[tm], bh[tn]);
#pragma unroll
            for (int tn = 0; tn < 4; tn++)
                LDM_X2(bl[tn][0], bl[tn][1], (bOff[tn] + 16384u + kb) ^ bXor[tn]);
#pragma unroll
            for (int tm = 0; tm < 4; tm++)
#pragma unroll
                for (int tn = 0; tn < 4; tn++)
                    MMA16816(acc[tm][tn], a[tm], bl[tn]);
#pragma unroll
            for (int tm = 0; tm < 4; tm++)
                LDM_X4(a[tm][0], a[tm][1], a[tm][2], a[tm][3],
                       (aOff[tm] + 16384u + kb) ^ aXor[tm]);
#pragma unroll
            for (int tm = 0; tm < 4; tm++)
#pragma unroll
                for (int tn = 0; tn < 4; tn++)
                    MMA16816(acc[tm][tn], a[tm], bh[tn]);
        }
    }

    // ---- epilogue: out = s_eff[b,oc]*y + bias[oc] ----
    const int gID = lane >> 2;
    const int t4  = lane & 3;
    const float* scRow = g_scale + (b << 9) + ocBase;
#pragma unroll
    for (int tn = 0; tn < 4; tn++) {
        const int col0 = wn0 + tn * 8 + t4 * 2;
        const float sc0 = scRow[col0],  sc1 = scRow[col0 + 1];
        const float bs0 = conv_bias[ocBase + col0];
        const float bs1 = conv_bias[ocBase + col0 + 1];
        float* o0 = out + (((size_t)(b * COUT + ocBase + col0)) * 32 + h0) * 32;
        float* o1 = out + (((size_t)(b * COUT + ocBase + col0 + 1)) * 32 + h0) * 32;
#pragma unroll
        for (int tm = 0; tm < 4; tm++) {
            const int mA = wm0 + tm * 16 + gID;       // rows mA and mA+8
            const int rA = mA >> 5, wA = mA & 31;
            const int mB = mA + 8;
            const int rB = mB >> 5, wB = mB & 31;
            o0[rA * 32 + wA] = acc[tm][tn][0] * sc0 + bs0;
            o1[rA * 32 + wA] = acc[tm][tn][1] * sc1 + bs1;
            o0[rB * 32 + wB] = acc[tm][tn][2] * sc0 + bs0;
            o1[rB * 32 + wB] = acc[tm][tn][3] * sc1 + bs1;
        }
    }
}

// ---------------------------------------------------------------------------
// Launch. Inputs: 0 x, 1 style_w, 2 conv_weight, 3 lin_w, 4 lin_b,
//                 5 mod_bias, 6 conv_bias
// ---------------------------------------------------------------------------
extern "C" void kernel_launch(void* const* d_in, const int* in_sizes, int n_in,
                              void* d_out, int out_size) {
    const float* x         = (const float*)d_in[0];
    const float* style_w   = (const float*)d_in[1];
    const float* conv_w    = (const float*)d_in[2];
    const float* lin_w     = (const float*)d_in[3];
    const float* lin_b     = (const float*)d_in[4];
    const float* mod_bias  = (const float*)d_in[5];
    const float* conv_bias = (const float*)d_in[6];
    float* out = (float*)d_out;

    cudaFuncSetAttribute(conv_mma_kernel,
                         cudaFuncAttributeMaxDynamicSharedMemorySize, SMEM_SZ);

    split_x_kernel<<<(NXP + 255) / 256, 256>>>(x);
    split_w_kernel<<<(NW + 255) / 256, 256>>>(conv_w);
    scale_kernel<<<COUT, 128>>>(conv_w, style_w, lin_w, lin_b, mod_bias);
    conv_mma_kernel<<<dim3(4, 128), 256, SMEM_SZ>>>(conv_bias, out);
}

// round 9
// speedup vs baseline: 3.0803x; 1.4942x over previous
#include <cuda_runtime.h>
#include <cuda_bf16.h>
#include <stdint.h>
#include <math.h>

// ---------------------------------------------------------------------------
// B=16, C_IN=512, C_OUT=512, K=3, LAT=256, H=W=32.
// Modulated conv == plain conv (raw weights) + per-(b,oc) scale + bias.
// Implicit GEMM on mma.sync bf16 (3-pass hi/lo split: xh*wh+xh*wl+xl*wh).
// Round-9: x pre-transposed to spatial-major xT[b][hp][wp][ic] so A tiles are
// cp.async-able; 2-stage double-buffered K loop (k=32 chunks, 144 iters);
// hi|lo packed in the same 128B SW128 row.
// ---------------------------------------------------------------------------
#define BATCH   16
#define CIN     512
#define COUT    512
#define LAT     256
#define KR      4608
#define XP      34
#define XPP     (XP * XP)            // 1156
#define NXT     (BATCH * XPP * CIN)  // 9,469,952 elements per array
#define NW      (COUT * CIN)         // per tap

#define EQ_LIN_F 0.08838834764831845f

// ---- device scratch (allocation-free) ----
__device__ __nv_bfloat16 g_xth[NXT];     // [b][hp][wp][ic] hi
__device__ __nv_bfloat16 g_xtl[NXT];     // [b][hp][wp][ic] lo
__device__ __nv_bfloat16 g_wh[9 * NW];   // [tap][oc][ic]
__device__ __nv_bfloat16 g_wl[9 * NW];
__device__ float         g_scale[BATCH * COUT];

// ---------------------------------------------------------------------------
// helpers
// ---------------------------------------------------------------------------
__device__ __forceinline__ uint32_t smem_u32(const void* p) {
    uint32_t a;
    asm("{ .reg .u64 t; cvta.to.shared.u64 t, %1; cvt.u32.u64 %0, t; }"
        : "=r"(a) : "l"(p));
    return a;
}
#define SW128(o) ((o) ^ ((((unsigned)(o)) >> 3) & 0x70u))

#define LDM_X4(r0, r1, r2, r3, a) \
    asm volatile("ldmatrix.sync.aligned.m8n8.x4.shared.b16 {%0,%1,%2,%3}, [%4];" \
        : "=r"(r0), "=r"(r1), "=r"(r2), "=r"(r3) : "r"(a))
#define LDM_X2(r0, r1, a) \
    asm volatile("ldmatrix.sync.aligned.m8n8.x2.shared.b16 {%0,%1}, [%2];" \
        : "=r"(r0), "=r"(r1) : "r"(a))

#define MMA16816(d, a, b) \
    asm volatile("mma.sync.aligned.m16n8k16.row.col.f32.bf16.bf16.f32 " \
        "{%0,%1,%2,%3}, {%4,%5,%6,%7}, {%8,%9}, {%0,%1,%2,%3};" \
        : "+f"((d)[0]), "+f"((d)[1]), "+f"((d)[2]), "+f"((d)[3]) \
        : "r"((a)[0]), "r"((a)[1]), "r"((a)[2]), "r"((a)[3]), \
          "r"((b)[0]), "r"((b)[1]))

#define CP16(dst, src) \
    asm volatile("cp.async.cg.shared.global [%0], [%1], 16;" :: "r"(dst), "l"(src))
#define CP_COMMIT()  asm volatile("cp.async.commit_group;")
#define CP_WAIT0()   asm volatile("cp.async.wait_group 0;" ::: "memory")
#define CP_WAIT1()   asm volatile("cp.async.wait_group 1;" ::: "memory")

// ---------------------------------------------------------------------------
// 1a) zero xT arrays (borders stay zero forever)
// ---------------------------------------------------------------------------
__global__ void zero_xt_kernel() {
    const int i = blockIdx.x * blockDim.x + threadIdx.x;
    if (i >= NXT / 8) return;
    const uint4 z = make_uint4(0, 0, 0, 0);
    ((uint4*)g_xth)[i] = z;
    ((uint4*)g_xtl)[i] = z;
}

// ---------------------------------------------------------------------------
// 1b) transpose + split x -> xT[b][h+1][w+1][ic] hi/lo. Tile 32ic x 32w.
//     grid (16, 512): bx -> ic0, by -> (b, h). Coalesced both sides.
// ---------------------------------------------------------------------------
__global__ void trans_x_kernel(const float* __restrict__ x) {
    __shared__ float tile[32][33];
    const int ic0 = blockIdx.x * 32;
    const int b   = blockIdx.y >> 5;
    const int h   = blockIdx.y & 31;
    const int tx = threadIdx.x, ty = threadIdx.y;
#pragma unroll
    for (int i = 0; i < 4; i++) {
        const int icl = ty + 8 * i;
        tile[icl][tx] = x[(((size_t)b * CIN + ic0 + icl) * 32 + h) * 32 + tx];
    }
    __syncthreads();
#pragma unroll
    for (int jj = 0; jj < 4; jj++) {
        const int j = ty + 8 * jj;
        const float v = tile[tx][j];
        const __nv_bfloat16 hi = __float2bfloat16(v);
        const size_t idx = ((size_t)(b * XP + h + 1) * XP + (j + 1)) * CIN + ic0 + tx;
        g_xth[idx] = hi;
        g_xtl[idx] = __float2bfloat16(v - __bfloat162float(hi));
    }
}

// ---------------------------------------------------------------------------
// 2) split + per-tap transpose weights -> g_wh/g_wl [tap][oc][ic]
// ---------------------------------------------------------------------------
__global__ void split_w_kernel(const float* __restrict__ w) {
    int i = blockIdx.x * blockDim.x + threadIdx.x;   // oc*512 + ic
    if (i >= NW) return;
    const float* src = w + (size_t)i * 9;
#pragma unroll
    for (int t = 0; t < 9; t++) {
        const float v = src[t];
        const __nv_bfloat16 h = __float2bfloat16(v);
        g_wh[(size_t)t * NW + i] = h;
        g_wl[(size_t)t * NW + i] = __float2bfloat16(v - __bfloat162float(h));
    }
}

// ---------------------------------------------------------------------------
// 3) per-(b,oc) effective scale (verified)
// ---------------------------------------------------------------------------
__global__ void scale_kernel(const float* __restrict__ W,
                             const float* __restrict__ style_w,
                             const float* __restrict__ lin_w,
                             const float* __restrict__ lin_b,
                             const float* __restrict__ mod_bias) {
    const int o = blockIdx.x;
    __shared__ float red[128];
    float ss = 0.f;
    const float* wrow = W + (size_t)o * KR;
    for (int i = threadIdx.x; i < KR; i += 128) {
        float v = wrow[i];
        ss += v * v;
    }
    red[threadIdx.x] = ss;
    __syncthreads();
#pragma unroll
    for (int s = 64; s > 0; s >>= 1) {
        if (threadIdx.x < s) red[threadIdx.x] += red[threadIdx.x + s];
        __syncthreads();
    }
    const float sumsq = red[0];
    if (threadIdx.x < BATCH) {
        const int b = threadIdx.x;
        const float* st = style_w + b * LAT;
        const float* lw = lin_w + (size_t)o * LAT;
        float dot = 0.f;
#pragma unroll 8
        for (int l = 0; l < LAT; l++) dot += st[l] * lw[l];
        const float eq_conv = sqrtf(2.0f / (float)KR);
        const float s = dot * EQ_LIN_F + lin_b[o] + 1.0f + mod_bias[o];
        g_scale[b * COUT + o] =
            eq_conv * s * rsqrtf(s * s * eq_conv * eq_conv * sumsq + 1e-8f);
    }
}

// ---------------------------------------------------------------------------
// 4) main mma.sync kernel, double-buffered.
//    CTA: M=128 spatial x N=128 oc; grid (4,128); 8 warps 2x4 -> 64x32 tiles.
//    144 iters (9 taps x 16 ic-chunks of 32). Stage (32KB): A[128m][128B row =
//    32ic hi | 32ic lo], B[128oc][same], SW128 rows. Fill it+1 via cp.async
//    while computing it.
// ---------------------------------------------------------------------------
#define ITERS   144
#define STAGE   32768
#define SMEM_SZ (2 * STAGE + 1024)

__global__ __launch_bounds__(256, 2)
void conv_mma_kernel(const float* __restrict__ conv_bias, float* __restrict__ out) {
    extern __shared__ __align__(1024) char dsm[];
    const uint32_t sb = smem_u32(dsm);
    const uint32_t tb = (sb + 1023u) & ~1023u;

    const int t    = threadIdx.x;
    const int wid  = t >> 5, lane = t & 31;
    const int ocBase = blockIdx.x * 128;
    const int mT = blockIdx.y;
    const int b  = mT >> 3;
    const int h0 = (mT & 7) * 4;

    const int wm0 = (wid & 1) * 64;
    const int wn0 = (wid >> 1) * 32;

    // fragment offsets (stage-relative) + row-XOR; address = base + ((off+kb)^xor)
    uint32_t aOff[4], aXor[4], bOff[4], bXor[4];
    {
        const int rA = lane & 15;
        const int ha = lane >> 4;
#pragma unroll
        for (int tm = 0; tm < 4; tm++) {
            const uint32_t off = (uint32_t)(wm0 + tm * 16 + rA) * 128u + ha * 16u;
            aOff[tm] = off;
            aXor[tm] = (off >> 3) & 0x70u;
        }
        const int rB = lane & 7;
        const int hb = (lane >> 3) & 1;
#pragma unroll
        for (int tn = 0; tn < 4; tn++) {
            const uint32_t off = (uint32_t)(wn0 + tn * 8 + rB) * 128u + hb * 16u;
            bOff[tn] = off;
            bXor[tn] = (off >> 3) & 0x70u;
        }
    }

    float acc[4][4][4];
#pragma unroll
    for (int i = 0; i < 4; i++)
#pragma unroll
        for (int j = 0; j < 4; j++)
#pragma unroll
            for (int k = 0; k < 4; k++) acc[i][j][k] = 0.f;

    // fill stage s for iteration it: 2048 cp16 = 8/thread (k even: A, k odd.. no:
    // i<1024 -> A (threads do 4 A then 4 B chunks; uniform per step, no diverge)
    auto fill_stage = [&](int s, int it) {
        const int tap = it >> 4;
        const int ic0 = (it & 15) << 5;
        const int dh = tap / 3, dw = tap - dh * 3;
        const uint32_t uA = tb + s * STAGE;
        const uint32_t uB = uA + 16384;
#pragma unroll
        for (int kk = 0; kk < 8; kk++) {
            const int i = kk * 256 + t;
            const int row = (i >> 3) & 127;
            const int q = i & 7;
            const int v = q >> 2;
            const int sub = q & 3;
            const uint32_t doff = SW128((uint32_t)(row << 7) + (v << 6) + (sub << 4));
            if (i < 1024) {
                const __nv_bfloat16* base = v ? g_xtl : g_xth;
                const size_t g = ((size_t)((b * XP + h0 + (row >> 5) + dh) * XP
                                           + (row & 31) + dw) << 9)
                               + ic0 + (sub << 3);
                CP16(uA + doff, base + g);
            } else {
                const __nv_bfloat16* base = v ? g_wl : g_wh;
                const size_t g = (size_t)tap * NW
                               + ((size_t)(ocBase + row) << 9) + ic0 + (sub << 3);
                CP16(uB + doff, base + g);
            }
        }
    };

    fill_stage(0, 0);
    CP_COMMIT();

    for (int it = 0; it < ITERS; it++) {
        const int s = it & 1;
        if (it + 1 < ITERS) {
            fill_stage(s ^ 1, it + 1);
            CP_COMMIT();
            CP_WAIT1();             // group for stage s complete
        } else {
            CP_WAIT0();
        }
        __syncthreads();

        const uint32_t uA = tb + s * STAGE;
        const uint32_t uB = uA + 16384;
#pragma unroll
        for (int ks = 0; ks < 2; ks++) {
            const uint32_t kb = ks * 32;          // hi at +kb, lo at +64+kb
            uint32_t a[4][4], bh[4][2], bl[4][2];
#pragma unroll
            for (int tn = 0; tn < 4; tn++)
                LDM_X2(bh[tn][0], bh[tn][1], uB + ((bOff[tn] + kb) ^ bXor[tn]));
#pragma unroll
            for (int tm = 0; tm < 4; tm++)
                LDM_X4(a[tm][0], a[tm][1], a[tm][2], a[tm][3],
                       uA + ((aOff[tm] + kb) ^ aXor[tm]));
#pragma unroll
            for (int tm = 0; tm < 4; tm++)
#pragma unroll
                for (int tn = 0; tn < 4; tn++)
                    MMA16816(acc[tm][tn], a[tm], bh[tn]);
#pragma unroll
            for (int tn = 0; tn < 4; tn++)
                LDM_X2(bl[tn][0], bl[tn][1],
                       uB + ((bOff[tn] + 64u + kb) ^ bXor[tn]));
#pragma unroll
            for (int tm = 0; tm < 4; tm++)
#pragma unroll
                for (int tn = 0; tn < 4; tn++)
                    MMA16816(acc[tm][tn], a[tm], bl[tn]);
#pragma unroll
            for (int tm = 0; tm < 4; tm++)
                LDM_X4(a[tm][0], a[tm][1], a[tm][2], a[tm][3],
                       uA + ((aOff[tm] + 64u + kb) ^ aXor[tm]));
#pragma unroll
            for (int tm = 0; tm < 4; tm++)
#pragma unroll
                for (int tn = 0; tn < 4; tn++)
                    MMA16816(acc[tm][tn], a[tm], bh[tn]);
        }
        __syncthreads();
    }

    // ---- epilogue: out = s_eff[b,oc]*y + bias[oc] (verified mapping) ----
    const int gID = lane >> 2;
    const int t4  = lane & 3;
    const float* scRow = g_scale + (b << 9) + ocBase;
#pragma unroll
    for (int tn = 0; tn < 4; tn++) {
        const int col0 = wn0 + tn * 8 + t4 * 2;
        const float sc0 = scRow[col0],  sc1 = scRow[col0 + 1];
        const float bs0 = conv_bias[ocBase + col0];
        const float bs1 = conv_bias[ocBase + col0 + 1];
        float* o0 = out + (((size_t)(b * COUT + ocBase + col0)) * 32 + h0) * 32;
        float* o1 = out + (((size_t)(b * COUT + ocBase + col0 + 1)) * 32 + h0) * 32;
#pragma unroll
        for (int tm = 0; tm < 4; tm++) {
            const int mA = wm0 + tm * 16 + gID;
            const int rA = mA >> 5, wA = mA & 31;
            const int mB = mA + 8;
            const int rB = mB >> 5, wB = mB & 31;
            o0[rA * 32 + wA] = acc[tm][tn][0] * sc0 + bs0;
            o1[rA * 32 + wA] = acc[tm][tn][1] * sc1 + bs1;
            o0[rB * 32 + wB] = acc[tm][tn][2] * sc0 + bs0;
            o1[rB * 32 + wB] = acc[tm][tn][3] * sc1 + bs1;
        }
    }
}

// ---------------------------------------------------------------------------
// Launch. Inputs: 0 x, 1 style_w, 2 conv_weight, 3 lin_w, 4 lin_b,
//                 5 mod_bias, 6 conv_bias
// ---------------------------------------------------------------------------
extern "C" void kernel_launch(void* const* d_in, const int* in_sizes, int n_in,
                              void* d_out, int out_size) {
    const float* x         = (const float*)d_in[0];
    const float* style_w   = (const float*)d_in[1];
    const float* conv_w    = (const float*)d_in[2];
    const float* lin_w     = (const float*)d_in[3];
    const float* lin_b     = (const float*)d_in[4];
    const float* mod_bias  = (const float*)d_in[5];
    const float* conv_bias = (const float*)d_in[6];
    float* out = (float*)d_out;

    cudaFuncSetAttribute(conv_mma_kernel,
                         cudaFuncAttributeMaxDynamicSharedMemorySize, SMEM_SZ);

    zero_xt_kernel<<<(NXT / 8 + 255) / 256, 256>>>();
    trans_x_kernel<<<dim3(16, 512), dim3(32, 8)>>>(x);
    split_w_kernel<<<(NW + 255) / 256, 256>>>(conv_w);
    scale_kernel<<<COUT, 128>>>(conv_w, style_w, lin_w, lin_b, mod_bias);
    conv_mma_kernel<<<dim3(4, 128), 256, SMEM_SZ>>>(conv_bias, out);
}